// round 6
// baseline (speedup 1.0000x reference)
#include <cuda_runtime.h>
#include <cstddef>

typedef unsigned long long u64;

__device__ __forceinline__ u64 pk2(float lo, float hi) {
    u64 r; asm("mov.b64 %0,{%1,%2};" : "=l"(r) : "f"(lo), "f"(hi)); return r;
}
__device__ __forceinline__ void upk2(u64 v, float& lo, float& hi) {
    asm("mov.b64 {%0,%1},%2;" : "=f"(lo), "=f"(hi) : "l"(v));
}
__device__ __forceinline__ void fma2(u64& d, u64 a, u64 b) {
    asm("fma.rn.f32x2 %0,%1,%2,%0;" : "+l"(d) : "l"(a), "l"(b));
}

// B=256, L=64, D=1024
// left'[k,d] = sum_l Wl[k,l]*left[l,d] + bl[k]   (same right)
// corr[i,d]  = sum_j left'[j,d]*right'[j+63-i,d] (i in [0,128), row 127 = 0)
// y[k,d]     = sum_c sum_t Wconv[k,c,t]*corr[c,d+t-1]  (zero pad in d)

namespace {
constexpr int Dc  = 1024;
constexpr int SAB = 66;                           // A/B row stride; col c at offset c
constexpr int SCr = 68;                           // corr row stride; col c at offset c
constexpr int OFF_A = 0;                          // 64 rows  left raw -> left'
constexpr int OFF_B = OFF_A + 64 * SAB;           // 192 rows zero-padded right raw -> right'
constexpr int OFF_C = OFF_B + 192 * SAB;          // 128 rows corr; aliased: W^T (ph1)
constexpr int WT_SZ = 64 * SCr;                   // 4352 per mat, 2 mats = 8704 = corr size
constexpr int SMEM_FLOATS = OFF_C + 128 * SCr;    // 25600 fl = 102400 B -> 2 CTAs/SM
constexpr int SMEM_BYTES  = SMEM_FLOATS * 4;
}

__global__ void __launch_bounds__(256, 2)
cc_fused_kernel(const float* __restrict__ left,  const float* __restrict__ right,
                const float* __restrict__ Wl,    const float* __restrict__ bl,
                const float* __restrict__ Wr,    const float* __restrict__ br,
                const float* __restrict__ Wconv, float* __restrict__ out)
{
    extern __shared__ float sm[];
    const int tid = threadIdx.x;
    const int b   = blockIdx.y;
    const int dg0 = blockIdx.x * 64;    // global d of tile col 1 (col 0 = d-1 halo)

    // ---------------- phase 0: stage raw tiles (+zero pads) and W^T ----------------
    const float* Lb = left  + (size_t)b * 65536;
    const float* Rb = right + (size_t)b * 65536;
    for (int i = tid; i < 64 * 66; i += 256) {
        int r = i / 66, c = i % 66;
        int d = dg0 + c - 1;
        float lv = 0.f, rv = 0.f;
        if ((unsigned)d < (unsigned)Dc) { lv = Lb[r * Dc + d]; rv = Rb[r * Dc + d]; }
        sm[OFF_A + r * SAB + c]          = lv;
        sm[OFF_B + (64 + r) * SAB + c]   = rv;   // right' rows 64..127
        sm[OFF_B + r * SAB + c]          = 0.f;  // pad rows 0..63
        sm[OFF_B + (128 + r) * SAB + c]  = 0.f;  // pad rows 128..191
    }
    for (int i = tid; i < 8192; i += 256) {      // W^T[l][k], stride 68, in corr region
        int which = i >> 12, r = i & 4095;
        int k = r >> 6, l = r & 63;
        sm[OFF_C + which * WT_SZ + l * SCr + k] = (which ? Wr : Wl)[r];
    }
    __syncthreads();

    // ---------------- phase 1: linears, k-packed f32x2 ----------------
    {
        const int col  = 1 + (tid & 63);          // interior col offset
        const int grp  = tid >> 6;
        const int mat  = grp >> 1;                // 0: left(A), 1: right(B')
        const int k0   = (grp & 1) * 32;
        const int base = mat ? (OFF_B + 64 * SAB) : OFF_A;

        float raw[64];
        #pragma unroll
        for (int l = 0; l < 64; ++l) raw[l] = sm[base + l * SAB + col];
        __syncthreads();                          // all raw cached before in-place writes

        const ulonglong2* w2 = reinterpret_cast<const ulonglong2*>(sm + OFF_C + mat * WT_SZ);
        u64 acc[16];
        #pragma unroll
        for (int p = 0; p < 16; ++p) acc[p] = 0ull;
        #pragma unroll 4
        for (int l = 0; l < 64; ++l) {
            u64 rp = pk2(raw[l], raw[l]);
            const ulonglong2* wr_ = w2 + l * 17 + (k0 >> 2);
            #pragma unroll
            for (int q = 0; q < 8; ++q) {
                ulonglong2 w = wr_[q];            // LDS.128 broadcast = 2 k-pairs
                fma2(acc[2 * q + 0], w.x, rp);
                fma2(acc[2 * q + 1], w.y, rp);
            }
        }
        const float* bias = mat ? br : bl;
        #pragma unroll
        for (int p = 0; p < 16; ++p) {
            float lo, hi; upk2(acc[p], lo, hi);
            sm[base + (k0 + 2 * p + 0) * SAB + col] = lo + __ldg(bias + k0 + 2 * p + 0);
            sm[base + (k0 + 2 * p + 1) * SAB + col] = hi + __ldg(bias + k0 + 2 * p + 1);
        }

        // halo cols (0 and 65): 2 mats x 2 cols x 64 k = 256 items
        const int hmat = tid >> 7;
        const int hoff = (tid & 64) ? 65 : 0;
        const int hk   = tid & 63;
        const int hbase = hmat ? (OFF_B + 64 * SAB) : OFF_A;
        float rawh[64];
        #pragma unroll
        for (int l = 0; l < 64; ++l) rawh[l] = sm[hbase + l * SAB + hoff];
        __syncthreads();                          // halo raw cached before halo writes
        const float* wt = sm + OFF_C + hmat * WT_SZ;
        float acs = 0.f;
        #pragma unroll
        for (int l = 0; l < 64; ++l) acs += wt[l * SCr + hk] * rawh[l];
        sm[hbase + hk * SAB + hoff] = acs + __ldg((hmat ? br : bl) + hk);
    }
    __syncthreads();

    // ---------------- phase 2: correlation, triangular paired blocks ----------------
    {
        const int cp = tid & 31;                  // col pair (2cp, 2cp+1)
        const int ig = tid >> 5;                  // 0..7
        const u64* ap = reinterpret_cast<const u64*>(sm + OFF_A) + cp;   // row stride 33
        const u64* bp = reinterpret_cast<const u64*>(sm + OFF_B) + cp;
        u64* cst = reinterpret_cast<u64*>(sm + OFF_C) + cp;              // row stride 34
        const u64 keep = (dg0 == 0 && cp == 0) ? 0xFFFFFFFF00000000ull : ~0ull;

        #pragma unroll 1
        for (int blk = 0; blk < 2; ++blk) {
            const int i0  = blk ? (64 + 8 * ig) : (8 * ig);
            const int jlo = blk ? (8 * ig) : 0;
            const int nch = blk ? (8 - ig) : (ig + 1);
            u64 acc[8], win[8];
            #pragma unroll
            for (int q = 0; q < 8; ++q) acc[q] = 0ull;
            #pragma unroll
            for (int q = 1; q < 8; ++q) win[q] = bp[(jlo + 127 - i0 - q) * 33];
            #pragma unroll 1
            for (int ch = 0; ch < nch; ++ch) {
                const int j0 = jlo + ch * 8;
                u64 a2[8];
                #pragma unroll
                for (int t = 0; t < 8; ++t) a2[t] = ap[(j0 + t) * 33];
                #pragma unroll
                for (int t = 0; t < 8; ++t) {
                    u64 nv = bp[(j0 + t + 127 - i0) * 33];
                    fma2(acc[0], a2[t], nv);
                    #pragma unroll
                    for (int q = 1; q < 8; ++q) fma2(acc[q], a2[t], win[q]);
                    #pragma unroll
                    for (int q = 7; q > 1; --q) win[q] = win[q - 1];
                    win[1] = nv;
                }
            }
            #pragma unroll
            for (int q = 0; q < 8; ++q) cst[(i0 + q) * 34] = acc[q] & keep;
        }

        // tail cols 64, 65: 2 cols x 128 i = 256 items
        const int hcol = (tid >> 7) ? 65 : 64;
        const int hi   = tid & 127;
        const int gd   = dg0 + hcol - 1;
        const bool valid = (unsigned)gd < (unsigned)Dc;
        float acs = 0.f;
        #pragma unroll
        for (int j = 0; j < 64; ++j)
            acs += sm[OFF_A + j * SAB + hcol] * sm[OFF_B + (j + 127 - hi) * SAB + hcol];
        sm[OFF_C + hi * SCr + hcol] = valid ? acs : 0.f;
    }

    // ---------------- phase 3: conv(128->64,k=3), 8d x 2k, k-packed ----------------
    const int dq = tid & 7, kq = tid >> 3;        // d0 = 8*dq, k = 2kq, 2kq+1
    const int d0 = 8 * dq;
    u64 acc[8];
    #pragma unroll
    for (int dd = 0; dd < 8; ++dd) acc[dd] = 0ull;

    u64* wp = reinterpret_cast<u64*>(sm + OFF_B); // wp[kq*192 + cl*3 + t] = {W[2kq],W[2kq+1]}
    #pragma unroll 1
    for (int half = 0; half < 2; ++half) {
        __syncthreads();   // corr written / prev-half weight reads done before restage
        for (int i = tid; i < 32 * 192; i += 256) {
            int kp = i / 192, r = i % 192;        // r = cl*3 + t
            const float* src = Wconv + half * 192 + r;
            wp[kp * 192 + r] = pk2(__ldg(src + (2 * kp) * 384),
                                   __ldg(src + (2 * kp + 1) * 384));
        }
        __syncthreads();
        const u64* wb = wp + kq * 192;
        #pragma unroll 2
        for (int cl = 0; cl < 64; ++cl) {
            const float* crow = sm + OFF_C + (half * 64 + cl) * SCr + d0;
            float4 cA = *reinterpret_cast<const float4*>(crow);
            float4 cB = *reinterpret_cast<const float4*>(crow + 4);
            float2 cC = *reinterpret_cast<const float2*>(crow + 8);
            u64 cv[10] = { pk2(cA.x, cA.x), pk2(cA.y, cA.y), pk2(cA.z, cA.z), pk2(cA.w, cA.w),
                           pk2(cB.x, cB.x), pk2(cB.y, cB.y), pk2(cB.z, cB.z), pk2(cB.w, cB.w),
                           pk2(cC.x, cC.x), pk2(cC.y, cC.y) };
            const u64* wr_ = wb + cl * 3;
            u64 w0 = wr_[0], w1 = wr_[1], w2 = wr_[2];
            #pragma unroll
            for (int dd = 0; dd < 8; ++dd) {
                fma2(acc[dd], w0, cv[dd]);
                fma2(acc[dd], w1, cv[dd + 1]);
                fma2(acc[dd], w2, cv[dd + 2]);
            }
        }
    }

    float lo[8], hi[8];
    #pragma unroll
    for (int dd = 0; dd < 8; ++dd) upk2(acc[dd], lo[dd], hi[dd]);
    float* ob = out + (size_t)b * 65536 + dg0 + d0;
    float* o0 = ob + (size_t)(2 * kq) * Dc;
    float* o1 = ob + (size_t)(2 * kq + 1) * Dc;
    *reinterpret_cast<float4*>(o0)     = make_float4(lo[0], lo[1], lo[2], lo[3]);
    *reinterpret_cast<float4*>(o0 + 4) = make_float4(lo[4], lo[5], lo[6], lo[7]);
    *reinterpret_cast<float4*>(o1)     = make_float4(hi[0], hi[1], hi[2], hi[3]);
    *reinterpret_cast<float4*>(o1 + 4) = make_float4(hi[4], hi[5], hi[6], hi[7]);
}

extern "C" void kernel_launch(void* const* d_in, const int* in_sizes, int n_in,
                              void* d_out, int out_size)
{
    (void)in_sizes; (void)n_in; (void)out_size;
    const float* left  = (const float*)d_in[0];
    const float* right = (const float*)d_in[1];
    const float* Wl    = (const float*)d_in[2];
    const float* bl    = (const float*)d_in[3];
    const float* Wr    = (const float*)d_in[4];
    const float* br    = (const float*)d_in[5];
    const float* Wconv = (const float*)d_in[6];
    float* out = (float*)d_out;

    cudaFuncSetAttribute(cc_fused_kernel,
                         cudaFuncAttributeMaxDynamicSharedMemorySize, SMEM_BYTES);
    dim3 grid(Dc / 64, 256, 1);   // 4096 CTAs: one batch x 64-wide d-tile
    cc_fused_kernel<<<grid, 256, SMEM_BYTES>>>(left, right, Wl, bl, Wr, br, Wconv, out);
}

// round 8
// speedup vs baseline: 1.2890x; 1.2890x over previous
#include <cuda_runtime.h>
#include <cstddef>

typedef unsigned long long u64;

__device__ __forceinline__ u64 pk2(float lo, float hi) {
    u64 r; asm("mov.b64 %0,{%1,%2};" : "=l"(r) : "f"(lo), "f"(hi)); return r;
}
__device__ __forceinline__ void upk2(u64 v, float& lo, float& hi) {
    asm("mov.b64 {%0,%1},%2;" : "=f"(lo), "=f"(hi) : "l"(v));
}
__device__ __forceinline__ void fma2(u64& d, u64 a, u64 b) {
    asm("fma.rn.f32x2 %0,%1,%2,%0;" : "+l"(d) : "l"(a), "l"(b));
}

// B=256, L=64, D=1024
// left'[k,d] = sum_l Wl[k,l]*left[l,d] + bl[k]   (same right)
// corr[i,d]  = sum_j left'[j,d]*right'[j+63-i,d] (i in [0,128), row 127 = 0)
// y[k,d]     = sum_c sum_t Wconv[k,c,t]*corr[c,d+t-1]  (zero pad in d)

namespace {
constexpr int Dc  = 1024;
constexpr int SAB = 66;                           // A/B row stride; col c at offset c
constexpr int SCr = 68;                           // corr row stride; col c at offset c
constexpr int OFF_A = 0;                          // 64 rows  left raw -> left'
constexpr int OFF_B = OFF_A + 64 * SAB;           // 192 rows zero-padded right raw -> right'
constexpr int OFF_C = OFF_B + 192 * SAB;          // 128 rows corr; aliased: W^T (ph1)
constexpr int WT_SZ = 64 * SCr;                   // 4352/mat; 2 mats = 8704 = corr size
constexpr int OFF_S = OFF_C + 128 * SCr;          // 512-float tail scratch
constexpr int SMEM_FLOATS = OFF_S + 512;          // 26112 fl = 104448 B -> 2 CTAs/SM
constexpr int SMEM_BYTES  = SMEM_FLOATS * 4;
constexpr int WPS = 193;                          // Wconv pair stride (u64) - conflict-free
}

__global__ void __launch_bounds__(256, 2)
cc_fused_kernel(const float* __restrict__ left,  const float* __restrict__ right,
                const float* __restrict__ Wl,    const float* __restrict__ bl,
                const float* __restrict__ Wr,    const float* __restrict__ br,
                const float* __restrict__ Wconv, float* __restrict__ out)
{
    extern __shared__ float sm[];
    const int tid = threadIdx.x;
    const int b   = blockIdx.y;
    const int dg0 = blockIdx.x * 64;    // global d of tile col 1 (col 0 = d-1 halo)

    // ---------------- phase 0: stage raw tiles (+zero pads) and W^T ----------------
    const float* Lb = left  + (size_t)b * 65536;
    const float* Rb = right + (size_t)b * 65536;
    for (int i = tid; i < 64 * 66; i += 256) {
        int r = i / 66, c = i % 66;
        int d = dg0 + c - 1;
        float lv = 0.f, rv = 0.f;
        if ((unsigned)d < (unsigned)Dc) { lv = Lb[r * Dc + d]; rv = Rb[r * Dc + d]; }
        sm[OFF_A + r * SAB + c]          = lv;
        sm[OFF_B + (64 + r) * SAB + c]   = rv;   // right' rows 64..127
        sm[OFF_B + r * SAB + c]          = 0.f;  // pad rows 0..63
        sm[OFF_B + (128 + r) * SAB + c]  = 0.f;  // pad rows 128..191
    }
    for (int i = tid; i < 8192; i += 256) {      // W^T[l][k], stride 68, in corr region
        int which = i >> 12, r = i & 4095;
        int k = r >> 6, l = r & 63;
        sm[OFF_C + which * WT_SZ + l * SCr + k] = (which ? Wr : Wl)[r];
    }
    __syncthreads();

    // ---------------- phase 1: linears, k-packed f32x2 ----------------
    {
        const int col  = 1 + (tid & 63);          // interior col offset (1..64)
        const int grp  = tid >> 6;
        const int mat  = grp >> 1;                // 0: left(A), 1: right(B')
        const int k0   = (grp & 1) * 32;
        const int base = mat ? (OFF_B + 64 * SAB) : OFF_A;

        float raw[64];
        #pragma unroll
        for (int l = 0; l < 64; ++l) raw[l] = sm[base + l * SAB + col];
        __syncthreads();                          // all raw cached before in-place writes

        const ulonglong2* w2 = reinterpret_cast<const ulonglong2*>(sm + OFF_C + mat * WT_SZ);
        u64 acc[16];
        #pragma unroll
        for (int p = 0; p < 16; ++p) acc[p] = 0ull;
        #pragma unroll 4
        for (int l = 0; l < 64; ++l) {
            u64 rp = pk2(raw[l], raw[l]);
            const ulonglong2* wr_ = w2 + l * 17 + (k0 >> 2);
            #pragma unroll
            for (int q = 0; q < 8; ++q) {
                ulonglong2 w = wr_[q];            // LDS.128 broadcast = 2 k-pairs
                fma2(acc[2 * q + 0], w.x, rp);
                fma2(acc[2 * q + 1], w.y, rp);
            }
        }
        const float* bias = mat ? br : bl;
        #pragma unroll
        for (int p = 0; p < 16; ++p) {
            float lo, hi; upk2(acc[p], lo, hi);
            sm[base + (k0 + 2 * p + 0) * SAB + col] = lo + __ldg(bias + k0 + 2 * p + 0);
            sm[base + (k0 + 2 * p + 1) * SAB + col] = hi + __ldg(bias + k0 + 2 * p + 1);
        }

        // halo cols (0 and 65): 2 mats x 2 cols x 64 k = 256 items
        const int hmat = tid >> 7;
        const int hoff = (tid & 64) ? 65 : 0;
        const int hk   = tid & 63;
        const int hbase = hmat ? (OFF_B + 64 * SAB) : OFF_A;
        float rawh[64];
        #pragma unroll
        for (int l = 0; l < 64; ++l) rawh[l] = sm[hbase + l * SAB + hoff];
        __syncthreads();                          // halo raw cached before halo writes
        const float* wt = sm + OFF_C + hmat * WT_SZ;
        float acs = 0.f;
        #pragma unroll
        for (int l = 0; l < 64; ++l) acs += wt[l * SCr + hk] * rawh[l];
        sm[hbase + hk * SAB + hoff] = acs + __ldg((hmat ? br : bl) + hk);
    }
    __syncthreads();

    // -------- phase 2a: copy tail cols (64,65) of A/B into contiguous scratch --------
    for (int i = tid; i < 512; i += 256) {
        float v;
        if (i < 128)       v = sm[OFF_A + (i & 63) * SAB + 64 + (i >> 6)];       // A64,A65
        else               v = sm[OFF_B + ((i - 128) % 192) * SAB + 64 + ((i - 128) / 192)];
        sm[OFF_S + i] = v;   // [0,64)=A64 [64,128)=A65 [128,320)=B64 [320,512)=B65
    }
    __syncthreads();

    // ---------------- phase 2b: correlation, triangular paired blocks ----------------
    {
        const int cp = tid & 31;                  // col pair (2cp, 2cp+1) -> cols 0..63
        const int ig = tid >> 5;                  // 0..7
        const u64* ap = reinterpret_cast<const u64*>(sm + OFF_A) + cp;   // row stride 33
        const u64* bp = reinterpret_cast<const u64*>(sm + OFF_B) + cp;
        u64* cst = reinterpret_cast<u64*>(sm + OFF_C) + cp;              // row stride 34
        const u64 keep = (dg0 == 0 && cp == 0) ? 0xFFFFFFFF00000000ull : ~0ull;

        #pragma unroll 1
        for (int blk = 0; blk < 2; ++blk) {
            const int i0  = blk ? (64 + 8 * ig) : (8 * ig);
            const int jlo = blk ? (8 * ig) : 0;
            const int nch = blk ? (8 - ig) : (ig + 1);
            u64 acc[8], win[8];
            #pragma unroll
            for (int q = 0; q < 8; ++q) acc[q] = 0ull;
            #pragma unroll
            for (int q = 1; q < 8; ++q) win[q] = bp[(jlo + 127 - i0 - q) * 33];
            #pragma unroll 1
            for (int ch = 0; ch < nch; ++ch) {
                const int j0 = jlo + ch * 8;
                u64 a2[8];
                #pragma unroll
                for (int t = 0; t < 8; ++t) a2[t] = ap[(j0 + t) * 33];
                #pragma unroll
                for (int t = 0; t < 8; ++t) {
                    u64 nv = bp[(j0 + t + 127 - i0) * 33];
                    fma2(acc[0], a2[t], nv);
                    #pragma unroll
                    for (int q = 1; q < 8; ++q) fma2(acc[q], a2[t], win[q]);
                    #pragma unroll
                    for (int q = 7; q > 1; --q) win[q] = win[q - 1];
                    win[1] = nv;
                }
            }
            #pragma unroll
            for (int q = 0; q < 8; ++q) cst[(i0 + q) * 34] = acc[q] & keep;
        }

        // tail cols 64, 65 from contiguous scratch: 2 cols x 128 i
        const int hsel = tid >> 7;                // 0 -> col 64, 1 -> col 65
        const int hcol = 64 + hsel;
        const int hi   = tid & 127;
        const int gd   = dg0 + hcol - 1;
        const bool valid = (unsigned)gd < (unsigned)Dc;
        const float* ah = sm + OFF_S + hsel * 64;
        const float* bh = sm + OFF_S + 128 + hsel * 192;
        float acs = 0.f;
        #pragma unroll
        for (int j = 0; j < 64; ++j)
            acs += ah[j] * bh[j + 127 - hi];      // stride-1 / broadcast: conflict-free
        sm[OFF_C + hi * SCr + hcol] = valid ? acs : 0.f;
    }

    // ---------------- phase 3: conv(128->64,k=3), 4d x 4k, padded weight pairs ----------------
    const int dq = tid & 15, kq = tid >> 4;       // d0 = 4*dq, k rows 4kq..4kq+3
    const int d0 = 4 * dq;
    u64 acc3[2][4];
    #pragma unroll
    for (int p = 0; p < 2; ++p)
        #pragma unroll
        for (int dd = 0; dd < 4; ++dd) acc3[p][dd] = 0ull;

    u64* wp = reinterpret_cast<u64*>(sm + OFF_B); // wp[kp*WPS + cl*3 + t] = {W[2kp],W[2kp+1]}
    #pragma unroll 1
    for (int half = 0; half < 2; ++half) {
        __syncthreads();   // corr written / prev-half weight reads done before restage
        for (int i = tid; i < 32 * 192; i += 256) {
            int kp = i / 192, r = i % 192;        // r = cl*3 + t
            const float* src = Wconv + half * 192 + r;
            wp[kp * WPS + r] = pk2(__ldg(src + (2 * kp) * 384),
                                   __ldg(src + (2 * kp + 1) * 384));
        }
        __syncthreads();
        const u64* wb = wp + (2 * kq) * WPS;
        #pragma unroll 4
        for (int cl = 0; cl < 64; ++cl) {
            const float* crow = sm + OFF_C + (half * 64 + cl) * SCr + d0;
            float4 c4 = *reinterpret_cast<const float4*>(crow);
            float2 ct = *reinterpret_cast<const float2*>(crow + 4);
            u64 cv[6] = { pk2(c4.x, c4.x), pk2(c4.y, c4.y), pk2(c4.z, c4.z),
                          pk2(c4.w, c4.w), pk2(ct.x, ct.x), pk2(ct.y, ct.y) };
            #pragma unroll
            for (int p = 0; p < 2; ++p) {
                const u64* wr_ = wb + p * WPS + cl * 3;
                u64 w0 = wr_[0], w1 = wr_[1], w2 = wr_[2];
                #pragma unroll
                for (int dd = 0; dd < 4; ++dd) {
                    fma2(acc3[p][dd], w0, cv[dd]);
                    fma2(acc3[p][dd], w1, cv[dd + 1]);
                    fma2(acc3[p][dd], w2, cv[dd + 2]);
                }
            }
        }
    }

    float* ob = out + (size_t)b * 65536 + dg0 + d0;
    #pragma unroll
    for (int p = 0; p < 2; ++p) {
        const int k0 = 4 * kq + 2 * p;
        #pragma unroll
        for (int dd = 0; dd < 4; ++dd) {
            float lo, hi; upk2(acc3[p][dd], lo, hi);
            ob[(size_t)k0 * Dc + dd]       = lo;
            ob[(size_t)(k0 + 1) * Dc + dd] = hi;
        }
    }
}

extern "C" void kernel_launch(void* const* d_in, const int* in_sizes, int n_in,
                              void* d_out, int out_size)
{
    (void)in_sizes; (void)n_in; (void)out_size;
    const float* left  = (const float*)d_in[0];
    const float* right = (const float*)d_in[1];
    const float* Wl    = (const float*)d_in[2];
    const float* bl    = (const float*)d_in[3];
    const float* Wr    = (const float*)d_in[4];
    const float* br    = (const float*)d_in[5];
    const float* Wconv = (const float*)d_in[6];
    float* out = (float*)d_out;

    cudaFuncSetAttribute(cc_fused_kernel,
                         cudaFuncAttributeMaxDynamicSharedMemorySize, SMEM_BYTES);
    dim3 grid(Dc / 64, 256, 1);   // 4096 CTAs: one batch x 64-wide d-tile
    cc_fused_kernel<<<grid, 256, SMEM_BYTES>>>(left, right, Wl, bl, Wr, br, Wconv, out);
}

// round 9
// speedup vs baseline: 1.5006x; 1.1642x over previous
#include <cuda_runtime.h>
#include <cstddef>

typedef unsigned long long u64;

__device__ __forceinline__ u64 pk2(float lo, float hi) {
    u64 r; asm("mov.b64 %0,{%1,%2};" : "=l"(r) : "f"(lo), "f"(hi)); return r;
}
__device__ __forceinline__ void upk2(u64 v, float& lo, float& hi) {
    asm("mov.b64 {%0,%1},%2;" : "=f"(lo), "=f"(hi) : "l"(v));
}
__device__ __forceinline__ void fma2(u64& d, u64 a, u64 b) {
    asm("fma.rn.f32x2 %0,%1,%2,%0;" : "+l"(d) : "l"(a), "l"(b));
}

// B=256, L=64, D=1024
// left'[k,d] = sum_l Wl[k,l]*left[l,d] + bl[k]   (same right)
// corr[i,d]  = sum_j left'[j,d]*right'[j+63-i,d] (i in [0,128), row 127 = 0)
// y[k,d]     = sum_c sum_t Wconv[k,c,t]*corr[c,d+t-1]  (zero pad in d)

namespace {
constexpr int Dc  = 1024;
constexpr int SAB = 66;                           // A/B row stride; col c at offset c
constexpr int SCr = 68;                           // corr / W^T row stride
constexpr int OFF_A = 0;                          // 64 rows  left'
constexpr int OFF_B = 64 * SAB;                   // 192 rows: pads + right' rows 64..127
constexpr int OFF_C = OFF_B + 192 * SAB;          // 128 rows corr; aliased: W^T (ph0/1)
constexpr int WT_SZ = 64 * SCr;                   // 4352/mat
constexpr int OFF_S = OFF_C + 128 * SCr;          // 512-float tail scratch
constexpr int SMEM_FLOATS = OFF_S + 512;          // 26112 fl = 104448 B -> 2 CTAs/SM
constexpr int SMEM_BYTES  = SMEM_FLOATS * 4;
constexpr int U64_B  = OFF_B / 2;                 // u64 index of B region (2112)
constexpr int WA_U2  = U64_B / 2;                 // ulonglong2 index of wA (1056)
constexpr int WB_U64 = U64_B + 32 * 65 * 2;       // u64 index of wB (6272; end 8352 <= 8448)
}

__global__ void __launch_bounds__(256, 2)
cc_fused_kernel(const float* __restrict__ left,  const float* __restrict__ right,
                const float* __restrict__ Wl,    const float* __restrict__ bl,
                const float* __restrict__ Wr,    const float* __restrict__ br,
                const float* __restrict__ Wconv, float* __restrict__ out)
{
    extern __shared__ float sm[];
    const int tid = threadIdx.x;
    const int b   = blockIdx.y;
    const int dg0 = blockIdx.x * 64;    // global d of tile col 1 (col 0 = d-1 halo)

    // ---- phase 0: raws into pad rows (B_raw rows 0..63, A_raw rows 128..191), W^T ----
    const float* Lb = left  + (size_t)b * 65536;
    const float* Rb = right + (size_t)b * 65536;
    for (int i = tid; i < 64 * 66; i += 256) {
        int r = i / 66, c = i % 66;
        int d = dg0 + c - 1;
        float lv = 0.f, rv = 0.f;
        if ((unsigned)d < (unsigned)Dc) { lv = Lb[r * Dc + d]; rv = Rb[r * Dc + d]; }
        sm[OFF_B + (128 + r) * SAB + c] = lv;    // A_raw
        sm[OFF_B + r * SAB + c]         = rv;    // B_raw
    }
    for (int i = tid; i < 8192; i += 256) {      // W^T[l][k], stride 68, in corr region
        int which = i >> 12, r = i & 4095;
        int k = r >> 6, l = r & 63;
        sm[OFF_C + which * WT_SZ + l * SCr + k] = (which ? Wr : Wl)[r];
    }
    __syncthreads();

    // ---- phase 1: linears, out-of-place, unique weight stream per warp ----
    {
        const int w    = tid >> 5, lane = tid & 31;
        const int mat  = w >> 2;                 // 0: left, 1: right
        const int kq   = w & 3,  k0 = kq * 16;
        const u64* rawp = reinterpret_cast<const u64*>(sm) + U64_B
                          + (mat ? 0 : 128 * 33) + lane;
        const ulonglong2* wt2 = reinterpret_cast<const ulonglong2*>(sm + OFF_C + mat * WT_SZ);
        const float* bias = mat ? br : bl;

        u64 acc[8][2];
        #pragma unroll
        for (int kp = 0; kp < 8; ++kp) {
            u64 bp_ = pk2(__ldg(bias + k0 + 2 * kp), __ldg(bias + k0 + 2 * kp + 1));
            acc[kp][0] = bp_; acc[kp][1] = bp_;
        }
        #pragma unroll 4
        for (int l = 0; l < 64; ++l) {
            u64 rp = rawp[l * 33];               // cols (2*lane, 2*lane+1)
            float c0, c1; upk2(rp, c0, c1);
            u64 p0 = pk2(c0, c0), p1 = pk2(c1, c1);
            const ulonglong2* wl_ = wt2 + l * 17 + 4 * kq;
            #pragma unroll
            for (int i = 0; i < 4; ++i) {
                ulonglong2 ww = wl_[i];          // k-pairs (2i, 2i+1)
                fma2(acc[2 * i][0],     ww.x, p0);
                fma2(acc[2 * i][1],     ww.x, p1);
                fma2(acc[2 * i + 1][0], ww.y, p0);
                fma2(acc[2 * i + 1][1], ww.y, p1);
            }
        }
        u64* ost = reinterpret_cast<u64*>(sm) + (mat ? (OFF_B + 64 * SAB) / 2 : 0) + lane;
        #pragma unroll
        for (int kp = 0; kp < 8; ++kp) {
            float a0, b0_, a1, b1_;
            upk2(acc[kp][0], a0, b0_);           // col 2*lane:   k even, k odd
            upk2(acc[kp][1], a1, b1_);           // col 2*lane+1
            ost[(k0 + 2 * kp) * 33]     = pk2(a0, a1);
            ost[(k0 + 2 * kp + 1) * 33] = pk2(b0_, b1_);
        }

        // tail cols 64,65: 2 mats x 2 cols x 64 k = 256 items (raws in pad rows: no hazard)
        const int hmat = tid >> 7;
        const int hoff = (tid & 64) ? 65 : 64;
        const int hk   = tid & 63;
        const float* rawh = sm + OFF_B + (hmat ? 0 : 128 * SAB) + hoff;
        const float* wt   = sm + OFF_C + hmat * WT_SZ;
        float acs = __ldg((hmat ? br : bl) + hk);
        #pragma unroll
        for (int l = 0; l < 64; ++l) acs += wt[l * SCr + hk] * rawh[l * SAB];
        sm[(hmat ? (OFF_B + 64 * SAB) : OFF_A) + hk * SAB + hoff] = acs;
    }
    __syncthreads();

    // ---- interlude: zero only the pad rows phase 2 touches; build tail scratch ----
    {
        u64* zb = reinterpret_cast<u64*>(sm) + U64_B;
        for (int i = tid; i < 16 * 33; i += 256) {
            int r = i / 33, c = i % 33;
            int row = (r < 8) ? (56 + r) : (120 + r);   // 56..63 and 128..135
            zb[row * 33 + c] = 0ull;
        }
        for (int i = tid; i < 512; i += 256) {   // [0,64)=A64 [64,128)=A65 [128,320)=B64 [320,512)=B65
            float v;
            if (i < 128) {
                v = sm[OFF_A + (i & 63) * SAB + 64 + (i >> 6)];
            } else {
                int t = i - 128, colsel = t / 192, row = t % 192;
                v = (row >= 64 && row < 128) ? sm[OFF_B + row * SAB + 64 + colsel] : 0.f;
            }
            sm[OFF_S + i] = v;
        }
    }
    __syncthreads();

    // ---- phase 2: correlation, triangular paired blocks ----
    {
        const int cp = tid & 31;                  // col pair (2cp, 2cp+1)
        const int ig = tid >> 5;                  // 0..7
        const u64* ap = reinterpret_cast<const u64*>(sm + OFF_A) + cp;   // row stride 33
        const u64* bp = reinterpret_cast<const u64*>(sm + OFF_B) + cp;
        u64* cst = reinterpret_cast<u64*>(sm + OFF_C) + cp;              // row stride 34
        const u64 keep = (dg0 == 0 && cp == 0) ? 0xFFFFFFFF00000000ull : ~0ull;

        #pragma unroll 1
        for (int blk = 0; blk < 2; ++blk) {
            const int i0  = blk ? (64 + 8 * ig) : (8 * ig);
            const int jlo = blk ? (8 * ig) : 0;
            const int nch = blk ? (8 - ig) : (ig + 1);
            u64 acc[8], win[8];
            #pragma unroll
            for (int q = 0; q < 8; ++q) acc[q] = 0ull;
            #pragma unroll
            for (int q = 1; q < 8; ++q) win[q] = bp[(jlo + 127 - i0 - q) * 33];
            #pragma unroll 1
            for (int ch = 0; ch < nch; ++ch) {
                const int j0 = jlo + ch * 8;
                u64 a2[8];
                #pragma unroll
                for (int t = 0; t < 8; ++t) a2[t] = ap[(j0 + t) * 33];
                #pragma unroll
                for (int t = 0; t < 8; ++t) {
                    u64 nv = bp[(j0 + t + 127 - i0) * 33];
                    fma2(acc[0], a2[t], nv);
                    #pragma unroll
                    for (int q = 1; q < 8; ++q) fma2(acc[q], a2[t], win[q]);
                    #pragma unroll
                    for (int q = 7; q > 1; --q) win[q] = win[q - 1];
                    win[1] = nv;
                }
            }
            #pragma unroll
            for (int q = 0; q < 8; ++q) cst[(i0 + q) * 34] = acc[q] & keep;
        }

        // tail cols 64,65 from contiguous scratch
        const int hsel = tid >> 7;
        const int hcol = 64 + hsel;
        const int hi   = tid & 127;
        const int gd   = dg0 + hcol - 1;
        const bool valid = (unsigned)gd < (unsigned)Dc;
        const float* ah = sm + OFF_S + hsel * 64;
        const float* bh = sm + OFF_S + 128 + hsel * 192;
        float acs = 0.f;
        #pragma unroll
        for (int j = 0; j < 64; ++j) acs += ah[j] * bh[j + 127 - hi];
        sm[OFF_C + hi * SCr + hcol] = valid ? acs : 0.f;
    }

    // ---- phase 3: conv(128->64,k=3), 4d x 4k, split vectorized weight pairs ----
    const int dq = tid & 15, kq = tid >> 4;
    const int d0 = 4 * dq;
    u64 acc3[2][4];
    #pragma unroll
    for (int p = 0; p < 2; ++p)
        #pragma unroll
        for (int dd = 0; dd < 4; ++dd) acc3[p][dd] = 0ull;

    const ulonglong2* wA = reinterpret_cast<const ulonglong2*>(sm) + WA_U2;
    const u64*        wB = reinterpret_cast<const u64*>(sm) + WB_U64;
    #pragma unroll 1
    for (int half = 0; half < 2; ++half) {
        __syncthreads();   // corr written / prev weight reads done before restage
        for (int i = tid; i < 2048; i += 256) {
            int kp = i >> 6, cl = i & 63;
            const float* s0 = Wconv + (2 * kp) * 384 + half * 192 + cl * 3;
            ulonglong2 v;
            v.x = pk2(__ldg(s0 + 0), __ldg(s0 + 384));
            v.y = pk2(__ldg(s0 + 1), __ldg(s0 + 385));
            (reinterpret_cast<ulonglong2*>(sm) + WA_U2)[kp * 65 + cl] = v;
            (reinterpret_cast<u64*>(sm) + WB_U64)[kp * 65 + cl] =
                pk2(__ldg(s0 + 2), __ldg(s0 + 386));
        }
        __syncthreads();
        #pragma unroll 4
        for (int cl = 0; cl < 64; ++cl) {
            const float* crow = sm + OFF_C + (half * 64 + cl) * SCr + d0;
            float4 cA = *reinterpret_cast<const float4*>(crow);
            float4 cB = *reinterpret_cast<const float4*>(crow + 4);
            u64 cv[6] = { pk2(cA.x, cA.x), pk2(cA.y, cA.y), pk2(cA.z, cA.z),
                          pk2(cA.w, cA.w), pk2(cB.x, cB.x), pk2(cB.y, cB.y) };
            #pragma unroll
            for (int p = 0; p < 2; ++p) {
                ulonglong2 wa = wA[(2 * kq + p) * 65 + cl];
                u64 wb = wB[(2 * kq + p) * 65 + cl];
                #pragma unroll
                for (int dd = 0; dd < 4; ++dd) {
                    fma2(acc3[p][dd], wa.x, cv[dd]);
                    fma2(acc3[p][dd], wa.y, cv[dd + 1]);
                    fma2(acc3[p][dd], wb,   cv[dd + 2]);
                }
            }
        }
    }

    float* ob = out + (size_t)b * 65536 + dg0 + d0;
    #pragma unroll
    for (int p = 0; p < 2; ++p) {
        const int k0 = 4 * kq + 2 * p;
        #pragma unroll
        for (int dd = 0; dd < 4; ++dd) {
            float lo, hi; upk2(acc3[p][dd], lo, hi);
            ob[(size_t)k0 * Dc + dd]       = lo;
            ob[(size_t)(k0 + 1) * Dc + dd] = hi;
        }
    }
}

extern "C" void kernel_launch(void* const* d_in, const int* in_sizes, int n_in,
                              void* d_out, int out_size)
{
    (void)in_sizes; (void)n_in; (void)out_size;
    const float* left  = (const float*)d_in[0];
    const float* right = (const float*)d_in[1];
    const float* Wl    = (const float*)d_in[2];
    const float* bl    = (const float*)d_in[3];
    const float* Wr    = (const float*)d_in[4];
    const float* br    = (const float*)d_in[5];
    const float* Wconv = (const float*)d_in[6];
    float* out = (float*)d_out;

    cudaFuncSetAttribute(cc_fused_kernel,
                         cudaFuncAttributeMaxDynamicSharedMemorySize, SMEM_BYTES);
    dim3 grid(Dc / 64, 256, 1);   // 4096 CTAs: one batch x 64-wide d-tile
    cc_fused_kernel<<<grid, 256, SMEM_BYTES>>>(left, right, Wl, bl, Wr, br, Wconv, out);
}